// round 1
// baseline (speedup 1.0000x reference)
#include <cuda_runtime.h>

#define NQ  10
#define DIM 1024          // 2^NQ
#define NL  4
#define TPB 256

__device__ __forceinline__ float2 cmul(float2 a, float2 b) {
    return make_float2(a.x * b.x - a.y * b.y, a.x * b.y + a.y * b.x);
}

__global__ __launch_bounds__(TPB) void qsim_kernel(
    const float* __restrict__ x,     // (B, 2*NQ)
    const float* __restrict__ w,     // (NL, NQ, 3)
    float* __restrict__ out)         // (B, NQ)
{
    __shared__ float2 sv[DIM];                 // statevector
    __shared__ float2 gmat[NL * NQ][4];        // fused RZ*RY*RZ matrices
    __shared__ unsigned short perm[2][DIM];    // fused CNOT-ring permutations
    __shared__ float2 venc[NQ][2];             // per-qubit encoded |0> columns
    __shared__ float  red[TPB / 32][NQ];       // reduction scratch

    const int t = threadIdx.x;
    const int s = blockIdx.x;
    const float inv_sqrt2 = 0.70710678118654752440f;
    const float pi_f      = 3.14159265358979323846f;

    // ---- precompute fused variational gates: U = RZ(w2)*RY(w1)*RZ(w0) ----
    if (t < NL * NQ) {
        float w0 = w[t * 3 + 0], w1 = w[t * 3 + 1], w2 = w[t * 3 + 2];
        float sb, cb; sincosf(0.5f * w1, &sb, &cb);
        float sp, cp; sincosf(0.5f * (w0 + w2), &sp, &cp);
        float sd, cd; sincosf(0.5f * (w0 - w2), &sd, &cd);
        gmat[t][0] = make_float2( cb * cp, -cb * sp);   // U00 = c*e^{-i(w0+w2)/2}
        gmat[t][1] = make_float2(-sb * cd, -sb * sd);   // U01 = -s*e^{+i(w0-w2)/2}
        gmat[t][2] = make_float2( sb * cd, -sb * sd);   // U10 =  s*e^{-i(w0-w2)/2}
        gmat[t][3] = make_float2( cb * cp,  cb * sp);   // U11 = c*e^{+i(w0+w2)/2}
    }
    // ---- per-sample encoding columns: v = RZ(phi)*RY(theta)*H |0> ----
    else if (t >= 64 && t < 64 + NQ) {
        int q = t - 64;
        float th = 0.5f * pi_f * (x[s * 2 * NQ + q]      + 1.0f);
        float ph = 0.5f * pi_f * (x[s * 2 * NQ + NQ + q] + 1.0f);
        float st, ct; sincosf(0.5f * th, &st, &ct);
        float sh, ch; sincosf(0.5f * ph, &sh, &ch);
        float a = inv_sqrt2 * (ct - st);
        float b = inv_sqrt2 * (ct + st);
        venc[q][0] = make_float2(a * ch, -a * sh);
        venc[q][1] = make_float2(b * ch,  b * sh);
    }
    // ---- fused CNOT-ring permutation tables (gather: new[j] = old[Finv(j)]) ----
    for (int j = t; j < 2 * DIM; j += TPB) {
        int type = j >> 10, idx = j & (DIM - 1);
        int off = type ? (NQ / 2) : 1;
        unsigned y = (unsigned)idx;
        // Finv = C_0 o C_1 o ... o C_9  (apply C_9 first); wire i <-> bit (NQ-1-i)
        #pragma unroll
        for (int i = NQ - 1; i >= 0; --i) {
            int bc = NQ - 1 - i;
            int bt = NQ - 1 - ((i + off) % NQ);
            y ^= ((y >> bc) & 1u) << bt;
        }
        perm[type][idx] = (unsigned short)y;
    }
    __syncthreads();

    // ---- build encoded product state directly (replaces 30 gate passes) ----
    {
        int base = t * 4;
        float2 p = venc[0][(base >> 9) & 1];
        #pragma unroll
        for (int i = 1; i < 8; ++i)
            p = cmul(p, venc[i][(base >> (9 - i)) & 1]);
        #pragma unroll
        for (int k = 0; k < 4; ++k) {
            float2 a = cmul(p, venc[8][(k >> 1) & 1]);
            a = cmul(a, venc[9][k & 1]);
            sv[base + k] = a;
        }
    }

    // ---- variational layers ----
    for (int layer = 0; layer < NL; ++layer) {
        for (int q = 0; q < NQ; ++q) {
            const float2 U00 = gmat[layer * NQ + q][0];
            const float2 U01 = gmat[layer * NQ + q][1];
            const float2 U10 = gmat[layer * NQ + q][2];
            const float2 U11 = gmat[layer * NQ + q][3];
            const int b  = NQ - 1 - q;
            const int lo = (1 << b) - 1;
            __syncthreads();
            #pragma unroll
            for (int k = 0; k < 2; ++k) {
                int p  = t + k * TPB;                       // pair index 0..511
                int i0 = ((p & ~lo) << 1) | (p & lo);
                int i1 = i0 | (1 << b);
                float2 a0 = sv[i0], a1 = sv[i1];
                float2 n0, n1;
                n0.x = U00.x * a0.x - U00.y * a0.y + U01.x * a1.x - U01.y * a1.y;
                n0.y = U00.x * a0.y + U00.y * a0.x + U01.x * a1.y + U01.y * a1.x;
                n1.x = U10.x * a0.x - U10.y * a0.y + U11.x * a1.x - U11.y * a1.y;
                n1.y = U10.x * a0.y + U10.y * a0.x + U11.x * a1.y + U11.y * a1.x;
                sv[i0] = n0; sv[i1] = n1;
            }
        }
        // fused CNOT ring: one permutation pass
        __syncthreads();
        const int type = layer & 1;
        float2 tmp[4];
        #pragma unroll
        for (int k = 0; k < 4; ++k)
            tmp[k] = sv[perm[type][t * 4 + k]];
        __syncthreads();
        #pragma unroll
        for (int k = 0; k < 4; ++k)
            sv[t * 4 + k] = tmp[k];
    }
    __syncthreads();

    // ---- <Z_i> readout ----
    float z[NQ];
    #pragma unroll
    for (int i = 0; i < NQ; ++i) z[i] = 0.0f;
    #pragma unroll
    for (int k = 0; k < 4; ++k) {
        int j = t * 4 + k;
        float2 a = sv[j];
        float pr = a.x * a.x + a.y * a.y;
        #pragma unroll
        for (int i = 0; i < NQ; ++i)
            z[i] += ((j >> (NQ - 1 - i)) & 1) ? -pr : pr;
    }
    #pragma unroll
    for (int i = 0; i < NQ; ++i) {
        #pragma unroll
        for (int o = 16; o > 0; o >>= 1)
            z[i] += __shfl_xor_sync(0xffffffffu, z[i], o);
    }
    if ((t & 31) == 0) {
        int wid = t >> 5;
        #pragma unroll
        for (int i = 0; i < NQ; ++i) red[wid][i] = z[i];
    }
    __syncthreads();
    if (t < NQ) {
        float acc = 0.0f;
        #pragma unroll
        for (int wid = 0; wid < TPB / 32; ++wid) acc += red[wid][t];
        out[s * NQ + t] = acc;
    }
}

extern "C" void kernel_launch(void* const* d_in, const int* in_sizes, int n_in,
                              void* d_out, int out_size) {
    const float* x = (const float*)d_in[0];
    const float* w = (const float*)d_in[1];
    float* out = (float*)d_out;
    int B = in_sizes[0] / (2 * NQ);   // 4096 flattened samples
    qsim_kernel<<<B, TPB>>>(x, w, out);
}

// round 2
// speedup vs baseline: 1.0564x; 1.0564x over previous
#include <cuda_runtime.h>

#define NQ    10
#define DIM   1024
#define NL    4
#define WARPS 4
#define TPB   (WARPS * 32)

__device__ __forceinline__ float2 cmul(float2 a, float2 b) {
    return make_float2(a.x * b.x - a.y * b.y, a.x * b.y + a.y * b.x);
}

// Apply fused 2x2 gate on register-index bit B (16 independent pairs, all static indices)
template<int B>
__device__ __forceinline__ void apply_gate(float2* r, const float2* __restrict__ U) {
    const float2 U00 = U[0], U01 = U[1], U10 = U[2], U11 = U[3];
    #pragma unroll
    for (int k = 0; k < 32; ++k) {
        if ((k & (1 << B)) == 0) {
            const int k1 = k | (1 << B);
            float2 a0 = r[k], a1 = r[k1];
            float2 n0, n1;
            n0.x = U00.x * a0.x - U00.y * a0.y + U01.x * a1.x - U01.y * a1.y;
            n0.y = U00.x * a0.y + U00.y * a0.x + U01.x * a1.y + U01.y * a1.x;
            n1.x = U10.x * a0.x - U10.y * a0.y + U11.x * a1.x - U11.y * a1.y;
            n1.y = U10.x * a0.y + U10.y * a0.x + U11.x * a1.y + U11.y * a1.x;
            r[k] = n0; r[k1] = n1;
        }
    }
}

__global__ __launch_bounds__(TPB) void qsim_kernel(
    const float* __restrict__ x,     // (B, 2*NQ)
    const float* __restrict__ w,     // (NL, NQ, 3)
    float* __restrict__ out)         // (B, NQ)
{
    __shared__ float2 scratch[WARPS][DIM];      // per-warp permutation scratch (32 KB)
    __shared__ float2 gmat[NL * NQ][4];         // fused RZ*RY*RZ gates
    __shared__ unsigned short Tp[2][DIM];       // S o Finv (CNOT ring composed with unswap)
    __shared__ float2 venc[WARPS][NQ][2];       // per-sample encoded |0> columns

    const int t    = threadIdx.x;
    const int lane = t & 31;
    const int wid  = t >> 5;
    const int s    = blockIdx.x * WARPS + wid;   // sample index
    const float inv_sqrt2 = 0.70710678118654752440f;
    const float pi_f      = 3.14159265358979323846f;

    // ---- fused variational gates: U = RZ(w2)*RY(w1)*RZ(w0) ----
    if (t < NL * NQ) {
        float w0 = w[t * 3 + 0], w1 = w[t * 3 + 1], w2 = w[t * 3 + 2];
        float sb, cb; sincosf(0.5f * w1, &sb, &cb);
        float sp, cp; sincosf(0.5f * (w0 + w2), &sp, &cp);
        float sd, cd; sincosf(0.5f * (w0 - w2), &sd, &cd);
        gmat[t][0] = make_float2( cb * cp, -cb * sp);
        gmat[t][1] = make_float2(-sb * cd, -sb * sd);
        gmat[t][2] = make_float2( sb * cd, -sb * sd);
        gmat[t][3] = make_float2( cb * cp,  cb * sp);
    }
    // ---- permutation tables: T[j] = S(Finv(j)), S = swap bits [9:5]<->[4:0] ----
    for (int j = t; j < 2 * DIM; j += TPB) {
        int type = j >> 10, idx = j & (DIM - 1);
        int off = type ? (NQ / 2) : 1;
        unsigned y = (unsigned)idx;
        #pragma unroll
        for (int i = NQ - 1; i >= 0; --i) {
            int bc = NQ - 1 - i;
            int bt = NQ - 1 - ((i + off) % NQ);
            y ^= ((y >> bc) & 1u) << bt;
        }
        Tp[type][idx] = (unsigned short)(((y & 31u) << 5) | (y >> 5));
    }
    // ---- per-sample encoding columns: v = RZ(phi)*RY(theta)*H |0> ----
    if (lane < NQ) {
        int q = lane;
        float th = 0.5f * pi_f * (x[s * 2 * NQ + q]      + 1.0f);
        float ph = 0.5f * pi_f * (x[s * 2 * NQ + NQ + q] + 1.0f);
        float st, ct; sincosf(0.5f * th, &st, &ct);
        float sh, ch; sincosf(0.5f * ph, &sh, &ch);
        float a = inv_sqrt2 * (ct - st);
        float b = inv_sqrt2 * (ct + st);
        venc[wid][q][0] = make_float2(a * ch, -a * sh);
        venc[wid][q][1] = make_float2(b * ch,  b * sh);
    }
    __syncthreads();

    // ---- build product state directly in registers ----
    // true index j = lane*32 + k; lane bit (4-q) <-> qubit q (0..4); reg bit (9-q) <-> qubit q (5..9)
    float2 r[32];
    {
        float2 L = venc[wid][0][(lane >> 4) & 1];
        L = cmul(L, venc[wid][1][(lane >> 3) & 1]);
        L = cmul(L, venc[wid][2][(lane >> 2) & 1]);
        L = cmul(L, venc[wid][3][(lane >> 1) & 1]);
        L = cmul(L, venc[wid][4][lane & 1]);
        #pragma unroll
        for (int k = 0; k < 32; ++k) {
            float2 a = cmul(L, venc[wid][5][(k >> 4) & 1]);
            a = cmul(a, venc[wid][6][(k >> 3) & 1]);
            a = cmul(a, venc[wid][7][(k >> 2) & 1]);
            a = cmul(a, venc[wid][8][(k >> 1) & 1]);
            a = cmul(a, venc[wid][9][k & 1]);
            r[k] = a;
        }
    }

    float2* sc = scratch[wid];

    #pragma unroll 1
    for (int layer = 0; layer < NL; ++layer) {
        const float2 (*G)[4] = &gmat[layer * NQ];
        // phase 1: qubits 5..9 live on reg bits 4..0
        apply_gate<4>(r, G[5]);
        apply_gate<3>(r, G[6]);
        apply_gate<2>(r, G[7]);
        apply_gate<1>(r, G[8]);
        apply_gate<0>(r, G[9]);
        // swap pass: registers <- state[S(m)]
        #pragma unroll
        for (int k = 0; k < 32; ++k) sc[lane * 32 + k] = r[k];
        __syncwarp();
        #pragma unroll
        for (int k = 0; k < 32; ++k) r[k] = sc[(k << 5) | lane];
        __syncwarp();
        // phase 2: qubits 0..4 now live on reg bits 4..0
        apply_gate<4>(r, G[0]);
        apply_gate<3>(r, G[1]);
        apply_gate<2>(r, G[2]);
        apply_gate<1>(r, G[3]);
        apply_gate<0>(r, G[4]);
        // CNOT ring + unswap in one gather: final[j] = swapped[S(Finv(j))]
        #pragma unroll
        for (int k = 0; k < 32; ++k) sc[lane * 32 + k] = r[k];
        __syncwarp();
        const unsigned short* T = Tp[layer & 1];
        #pragma unroll
        for (int k = 0; k < 32; ++k) r[k] = sc[T[lane * 32 + k]];
        __syncwarp();
    }

    // ---- <Z_q> readout (all in registers + shuffles) ----
    float pr_tot = 0.0f;
    float zb0 = 0.f, zb1 = 0.f, zb2 = 0.f, zb3 = 0.f, zb4 = 0.f;
    #pragma unroll
    for (int k = 0; k < 32; ++k) {
        float p = r[k].x * r[k].x + r[k].y * r[k].y;
        pr_tot += p;
        zb4 += (k & 16) ? -p : p;
        zb3 += (k & 8)  ? -p : p;
        zb2 += (k & 4)  ? -p : p;
        zb1 += (k & 2)  ? -p : p;
        zb0 += (k & 1)  ? -p : p;
    }
    float zq[NQ];
    zq[0] = ((lane >> 4) & 1) ? -pr_tot : pr_tot;
    zq[1] = ((lane >> 3) & 1) ? -pr_tot : pr_tot;
    zq[2] = ((lane >> 2) & 1) ? -pr_tot : pr_tot;
    zq[3] = ((lane >> 1) & 1) ? -pr_tot : pr_tot;
    zq[4] = (lane & 1)        ? -pr_tot : pr_tot;
    zq[5] = zb4; zq[6] = zb3; zq[7] = zb2; zq[8] = zb1; zq[9] = zb0;
    #pragma unroll
    for (int q = 0; q < NQ; ++q) {
        #pragma unroll
        for (int o = 16; o > 0; o >>= 1)
            zq[q] += __shfl_xor_sync(0xffffffffu, zq[q], o);
    }
    if (lane == 0) {
        #pragma unroll
        for (int q = 0; q < NQ; ++q)
            out[s * NQ + q] = zq[q];
    }
}

extern "C" void kernel_launch(void* const* d_in, const int* in_sizes, int n_in,
                              void* d_out, int out_size) {
    const float* x = (const float*)d_in[0];
    const float* w = (const float*)d_in[1];
    float* out = (float*)d_out;
    int B = in_sizes[0] / (2 * NQ);   // 4096 flattened samples
    qsim_kernel<<<B / WARPS, TPB>>>(x, w, out);
}

// round 3
// speedup vs baseline: 1.4411x; 1.3642x over previous
#include <cuda_runtime.h>

#define NQ    10
#define DIM   1024
#define NL    4
#define WARPS 4
#define TPB   (WARPS * 32)

typedef unsigned long long u64;

__device__ __forceinline__ u64 pack2(float x, float y) {
    u64 r; asm("mov.b64 %0, {%1,%2};" : "=l"(r) : "f"(x), "f"(y)); return r;
}
__device__ __forceinline__ u64 swp(u64 v) {
    u64 r;
    asm("{\n\t.reg .b32 lo, hi;\n\tmov.b64 {lo,hi}, %1;\n\tmov.b64 %0, {hi,lo};\n\t}"
        : "=l"(r) : "l"(v));
    return r;
}
__device__ __forceinline__ u64 ffma2(u64 a, u64 b, u64 c) {
    u64 d; asm("fma.rn.f32x2 %0, %1, %2, %3;" : "=l"(d) : "l"(a), "l"(b), "l"(c)); return d;
}
__device__ __forceinline__ u64 fmul2(u64 a, u64 b) {
    u64 d; asm("mul.rn.f32x2 %0, %1, %2;" : "=l"(d) : "l"(a), "l"(b)); return d;
}
__device__ __forceinline__ float2 cmulf(float2 a, float2 b) {
    return make_float2(a.x * b.x - a.y * b.y, a.x * b.y + a.y * b.x);
}

// Gate on register-index bit B (packed complex, f32x2 math).
// Coeff layout: C = {c00,d00,c01,d01,c10,d10,c11,d11}, cE=(re,re), dE=(-im,im).
template<int B>
__device__ __forceinline__ void gate_reg(u64* r, const u64* __restrict__ C) {
    const u64 c00 = C[0], d00 = C[1], c01 = C[2], d01 = C[3];
    const u64 c10 = C[4], d10 = C[5], c11 = C[6], d11 = C[7];
    #pragma unroll
    for (int k = 0; k < 32; ++k) {
        if ((k & (1 << B)) == 0) {
            const int k1 = k | (1 << B);
            u64 a0 = r[k], a1 = r[k1];
            u64 s0 = swp(a0), s1 = swp(a1);
            r[k]  = ffma2(c00, a0, ffma2(d00, s0, ffma2(c01, a1, fmul2(d01, s1))));
            r[k1] = ffma2(c10, a0, ffma2(d10, s0, ffma2(c11, a1, fmul2(d11, s1))));
        }
    }
}

// Gate on lane-index bit (xor distance D): partner via shuffle,
// coefficient roles swapped by own bit (selected once per gate).
template<int D>
__device__ __forceinline__ void gate_shfl(u64* r, const u64* __restrict__ C, int lane) {
    const bool b = (lane & D) != 0;
    const u64 cA = b ? C[6] : C[0];
    const u64 dA = b ? C[7] : C[1];
    const u64 cB = b ? C[4] : C[2];
    const u64 dB = b ? C[5] : C[3];
    #pragma unroll
    for (int k = 0; k < 32; ++k) {
        u64 own = r[k];
        u64 par = __shfl_xor_sync(0xffffffffu, own, D);
        r[k] = ffma2(cA, own, ffma2(dA, swp(own), ffma2(cB, par, fmul2(dB, swp(par)))));
    }
}

__global__ __launch_bounds__(TPB, 4) void qsim_kernel(
    const float* __restrict__ x,     // (B, 2*NQ)
    const float* __restrict__ w,     // (NL, NQ, 3)
    float* __restrict__ out)         // (B, NQ)
{
    __shared__ u64 scratch[WARPS][DIM];        // swizzled permutation scratch (32 KB)
    __shared__ u64 gmat[NL * NQ][8];           // packed fused-gate coefficients
    __shared__ unsigned short Tp[2][DIM];      // swizzled CNOT-ring gather tables
    __shared__ float2 venc[WARPS][NQ][2];      // per-sample encoded |0> columns

    const int t    = threadIdx.x;
    const int lane = t & 31;
    const int wid  = t >> 5;
    const int s    = blockIdx.x * WARPS + wid;
    const float inv_sqrt2 = 0.70710678118654752440f;
    const float pi_f      = 3.14159265358979323846f;

    // ---- fused variational gates: U = RZ(w2)*RY(w1)*RZ(w0), packed for f32x2 ----
    if (t < NL * NQ) {
        float w0 = w[t * 3 + 0], w1 = w[t * 3 + 1], w2 = w[t * 3 + 2];
        float sb, cb; sincosf(0.5f * w1, &sb, &cb);
        float sp, cp; sincosf(0.5f * (w0 + w2), &sp, &cp);
        float sd, cd; sincosf(0.5f * (w0 - w2), &sd, &cd);
        float2 U00 = make_float2( cb * cp, -cb * sp);
        float2 U01 = make_float2(-sb * cd, -sb * sd);
        float2 U10 = make_float2( sb * cd, -sb * sd);
        float2 U11 = make_float2( cb * cp,  cb * sp);
        gmat[t][0] = pack2(U00.x, U00.x);  gmat[t][1] = pack2(-U00.y, U00.y);
        gmat[t][2] = pack2(U01.x, U01.x);  gmat[t][3] = pack2(-U01.y, U01.y);
        gmat[t][4] = pack2(U10.x, U10.x);  gmat[t][5] = pack2(-U10.y, U10.y);
        gmat[t][6] = pack2(U11.x, U11.x);  gmat[t][7] = pack2(-U11.y, U11.y);
    }
    // ---- CNOT-ring gather tables, stored & targeted with XOR swizzle ----
    // phys(j) = (j & ~31) | ((j ^ (j>>5)) & 31)
    for (int j = t; j < 2 * DIM; j += TPB) {
        int type = j >> 10, idx = j & (DIM - 1);
        int off = type ? (NQ / 2) : 1;
        unsigned y = (unsigned)idx;
        #pragma unroll
        for (int i = NQ - 1; i >= 0; --i) {
            int bc = NQ - 1 - i;
            int bt = NQ - 1 - ((i + off) % NQ);
            y ^= ((y >> bc) & 1u) << bt;
        }
        unsigned py   = (y   & ~31u) | ((y   ^ (y   >> 5)) & 31u);
        unsigned pidx = (idx & ~31u) | ((idx ^ (idx >> 5)) & 31u);
        Tp[type][pidx] = (unsigned short)py;
    }
    // ---- per-sample encoding columns: v = RZ(phi)*RY(theta)*H |0> ----
    if (lane < NQ) {
        int q = lane;
        float th = 0.5f * pi_f * (x[s * 2 * NQ + q]      + 1.0f);
        float ph = 0.5f * pi_f * (x[s * 2 * NQ + NQ + q] + 1.0f);
        float st, ct; sincosf(0.5f * th, &st, &ct);
        float sh, ch; sincosf(0.5f * ph, &sh, &ch);
        float a = inv_sqrt2 * (ct - st);
        float b = inv_sqrt2 * (ct + st);
        venc[wid][q][0] = make_float2(a * ch, -a * sh);
        venc[wid][q][1] = make_float2(b * ch,  b * sh);
    }
    __syncthreads();

    // ---- build product state in registers (packed complex) ----
    // j = lane*32 + k ; j bit (9-q) <-> qubit q
    u64 r[32];
    {
        float2 L = venc[wid][0][(lane >> 4) & 1];
        L = cmulf(L, venc[wid][1][(lane >> 3) & 1]);
        L = cmulf(L, venc[wid][2][(lane >> 2) & 1]);
        L = cmulf(L, venc[wid][3][(lane >> 1) & 1]);
        L = cmulf(L, venc[wid][4][lane & 1]);
        #pragma unroll
        for (int k = 0; k < 32; ++k) {
            float2 a = cmulf(L, venc[wid][5][(k >> 4) & 1]);
            a = cmulf(a, venc[wid][6][(k >> 3) & 1]);
            a = cmulf(a, venc[wid][7][(k >> 2) & 1]);
            a = cmulf(a, venc[wid][8][(k >> 1) & 1]);
            a = cmulf(a, venc[wid][9][k & 1]);
            r[k] = pack2(a.x, a.y);
        }
    }

    u64* sc = scratch[wid];
    const int base = lane << 5;

    #pragma unroll 1
    for (int layer = 0; layer < NL; ++layer) {
        const u64 (*G)[8] = &gmat[layer * NQ];
        // qubits 0..4 on lane bits (shuffle gates)
        gate_shfl<16>(r, G[0], lane);
        gate_shfl<8>(r, G[1], lane);
        gate_shfl<4>(r, G[2], lane);
        gate_shfl<2>(r, G[3], lane);
        gate_shfl<1>(r, G[4], lane);
        // qubits 5..9 on register bits
        gate_reg<4>(r, G[5]);
        gate_reg<3>(r, G[6]);
        gate_reg<2>(r, G[7]);
        gate_reg<1>(r, G[8]);
        gate_reg<0>(r, G[9]);
        // fused CNOT ring: swizzled store + table gather
        #pragma unroll
        for (int k = 0; k < 32; ++k)
            sc[base | (k ^ lane)] = r[k];
        __syncwarp();
        const unsigned short* T = Tp[layer & 1];
        #pragma unroll
        for (int k = 0; k < 32; ++k)
            r[k] = sc[T[base | (k ^ lane)]];
        __syncwarp();
    }

    // ---- <Z_q> readout ----
    float pr_tot = 0.0f;
    float zb0 = 0.f, zb1 = 0.f, zb2 = 0.f, zb3 = 0.f, zb4 = 0.f;
    #pragma unroll
    for (int k = 0; k < 32; ++k) {
        float re = __uint_as_float((unsigned)(r[k] & 0xffffffffu));
        float im = __uint_as_float((unsigned)(r[k] >> 32));
        float p = re * re + im * im;
        pr_tot += p;
        zb4 += (k & 16) ? -p : p;
        zb3 += (k & 8)  ? -p : p;
        zb2 += (k & 4)  ? -p : p;
        zb1 += (k & 2)  ? -p : p;
        zb0 += (k & 1)  ? -p : p;
    }
    float zq[NQ];
    zq[0] = ((lane >> 4) & 1) ? -pr_tot : pr_tot;
    zq[1] = ((lane >> 3) & 1) ? -pr_tot : pr_tot;
    zq[2] = ((lane >> 2) & 1) ? -pr_tot : pr_tot;
    zq[3] = ((lane >> 1) & 1) ? -pr_tot : pr_tot;
    zq[4] = (lane & 1)        ? -pr_tot : pr_tot;
    zq[5] = zb4; zq[6] = zb3; zq[7] = zb2; zq[8] = zb1; zq[9] = zb0;
    #pragma unroll
    for (int q = 0; q < NQ; ++q) {
        #pragma unroll
        for (int o = 16; o > 0; o >>= 1)
            zq[q] += __shfl_xor_sync(0xffffffffu, zq[q], o);
    }
    if (lane == 0) {
        #pragma unroll
        for (int q = 0; q < NQ; ++q)
            out[s * NQ + q] = zq[q];
    }
}

extern "C" void kernel_launch(void* const* d_in, const int* in_sizes, int n_in,
                              void* d_out, int out_size) {
    const float* x = (const float*)d_in[0];
    const float* w = (const float*)d_in[1];
    float* out = (float*)d_out;
    int B = in_sizes[0] / (2 * NQ);   // 4096 flattened samples
    qsim_kernel<<<B / WARPS, TPB>>>(x, w, out);
}